// round 2
// baseline (speedup 1.0000x reference)
#include <cuda_runtime.h>
#include <cuda_bf16.h>
#include <math.h>

// Scratch (no allocations allowed): per-block partials + completion counter.
// Every g_part slot used in a launch is rewritten that launch, so no zeroing
// pass is needed. g_count self-resets to 0 in the last block -> the whole
// kernel_launch is deterministic across CUDA-graph replays.
#define MAX_BLOCKS 4096
__device__ float g_part[MAX_BLOCKS];
__device__ unsigned int g_count = 0;

__global__ void __launch_bounds__(256) nll_fused_kernel(
    const float* __restrict__ pred,          // (n, 8) fp32, channel 0 used
    const unsigned char* __restrict__ mask,  // (n,) bool (1 byte)
    float* __restrict__ out,
    int n)
{
    const int n4 = n >> 2;                   // n divisible by 4 here (4M)
    const int tid = blockIdx.x * blockDim.x + threadIdx.x;
    const int stride = gridDim.x * blockDim.x;
    const uchar4* __restrict__ mask4 = (const uchar4*)mask;

    float s = 0.0f;

    // 4 elements per thread per iteration: one coalesced 32-bit mask load +
    // 4 independent stride-8 pred loads (one 32B sector each) -> 5 LDGs of
    // MLP per iteration, fully sector-coalesced across the warp.
    for (int i = tid; i < n4; i += stride) {
        uchar4 m = __ldg(&mask4[i]);
        const float* base = pred + (size_t)i * 32;
        float p0 = __ldg(base + 0);
        float p1 = __ldg(base + 8);
        float p2 = __ldg(base + 16);
        float p3 = __ldg(base + 24);
        s += m.x ? logf(p0) : log1pf(-p0);
        s += m.y ? logf(p1) : log1pf(-p1);
        s += m.z ? logf(p2) : log1pf(-p2);
        s += m.w ? logf(p3) : log1pf(-p3);
    }

    // Tail (n not multiple of 4) — handled by thread 0 of block 0 only.
    if (blockIdx.x == 0 && threadIdx.x == 0) {
        for (int i = n4 << 2; i < n; i++) {
            float p = pred[(size_t)i * 8];
            s += mask[i] ? logf(p) : log1pf(-p);
        }
    }

    // Warp reduction (float; each thread summed only ~8 values).
    #pragma unroll
    for (int o = 16; o > 0; o >>= 1)
        s += __shfl_xor_sync(0xFFFFFFFFu, s, o);

    __shared__ float warp_sums[8];
    const int lane = threadIdx.x & 31;
    const int warp = threadIdx.x >> 5;
    if (lane == 0) warp_sums[warp] = s;
    __syncthreads();

    if (warp == 0) {
        float bs = (lane < (blockDim.x >> 5)) ? warp_sums[lane] : 0.0f;
        #pragma unroll
        for (int o = 4; o > 0; o >>= 1)
            bs += __shfl_xor_sync(0xFFFFFFFFu, bs, o);
        if (lane == 0) g_part[blockIdx.x] = bs;
    }

    // Elect the last block to finish (threadFenceReduction pattern).
    __shared__ bool is_last;
    __threadfence();
    if (threadIdx.x == 0) {
        unsigned int c = atomicAdd(&g_count, 1u);
        is_last = (c == gridDim.x - 1);
    }
    __syncthreads();

    if (is_last) {
        // Sum all block partials in double for a near-exact total.
        double d = 0.0;
        for (int i = threadIdx.x; i < (int)gridDim.x; i += blockDim.x)
            d += (double)g_part[i];

        #pragma unroll
        for (int o = 16; o > 0; o >>= 1)
            d += __shfl_xor_sync(0xFFFFFFFFu, d, o);

        __shared__ double dwarp[8];
        if (lane == 0) dwarp[warp] = d;
        __syncthreads();
        if (warp == 0) {
            double bd = (lane < (blockDim.x >> 5)) ? dwarp[lane] : 0.0;
            #pragma unroll
            for (int o = 4; o > 0; o >>= 1)
                bd += __shfl_xor_sync(0xFFFFFFFFu, bd, o);
            if (lane == 0) {
                out[0] = (float)(-bd * (1.0 / 256.0));
                g_count = 0;  // self-reset for next graph replay
            }
        }
    }
}

extern "C" void kernel_launch(void* const* d_in, const int* in_sizes, int n_in,
                              void* d_out, int out_size)
{
    const float* pred = (const float*)d_in[0];
    const unsigned char* mask = (const unsigned char*)d_in[1];
    float* out = (float*)d_out;

    int n = in_sizes[1];                 // 4,194,304
    int n4 = n >> 2;

    int blocks = (n4 + 255) / 256;       // one element-group per thread ideal
    if (blocks > 2048) blocks = 2048;    // 2048*256 threads -> 2 iters/thread
    if (blocks < 1) blocks = 1;

    nll_fused_kernel<<<blocks, 256>>>(pred, mask, out, n);
}

// round 3
// speedup vs baseline: 1.2111x; 1.2111x over previous
#include <cuda_runtime.h>
#include <cuda_bf16.h>
#include <math.h>

// Scratch (no allocations allowed): per-block partials + completion counter.
// Every g_part slot used in a launch is rewritten that launch; g_count
// self-resets to 0 in the last block -> deterministic across graph replays.
#define MAX_BLOCKS 4096
__device__ float g_part[MAX_BLOCKS];
__device__ unsigned int g_count = 0;

#define TPB 256
#define ILP 8

__global__ void __launch_bounds__(TPB) nll_fused_kernel(
    const float* __restrict__ pred,          // (n, 8) fp32, channel 0 used
    const unsigned char* __restrict__ mask,  // (n,) bool (1 byte)
    float* __restrict__ out,
    int n)
{
    const int tid = blockIdx.x * TPB + threadIdx.x;
    const int stride = gridDim.x * TPB;

    float s = 0.0f;

    if (n == stride * ILP) {
        // Fast path: exactly ILP strided elements per thread.
        // Front-batch ALL 16 loads (8 pred sectors + 8 mask bytes) before any
        // compute -> MLP_p1 = 16 independent LDGs per thread. Lane l of each
        // warp hits consecutive 32B sectors (pred stride = 8 floats = 1 sector),
        // so every fetched sector is fully consumed.
        float p[ILP];
        unsigned char m[ILP];
        #pragma unroll
        for (int k = 0; k < ILP; k++) {
            int e = tid + k * stride;
            p[k] = __ldg(&pred[(size_t)e * 8]);
            m[k] = __ldg(&mask[e]);
        }
        #pragma unroll
        for (int k = 0; k < ILP; k++) {
            // log(p) if masked else log(1-p). 1-p is exact for p>=0.5
            // (Sterbenz) and <=0.5ulp otherwise; per-element error ~2e-7,
            // random-sign -> negligible in the 4M-term sum vs 1e-3 tolerance.
            float q = m[k] ? p[k] : 1.0f - p[k];
            s += logf(q);
        }
    } else {
        // Generic fallback (any n).
        #pragma unroll 4
        for (int i = tid; i < n; i += stride) {
            float p = __ldg(&pred[(size_t)i * 8]);
            s += mask[i] ? logf(p) : log1pf(-p);
        }
    }

    // Warp reduction.
    #pragma unroll
    for (int o = 16; o > 0; o >>= 1)
        s += __shfl_xor_sync(0xFFFFFFFFu, s, o);

    __shared__ float warp_sums[TPB / 32];
    const int lane = threadIdx.x & 31;
    const int warp = threadIdx.x >> 5;
    if (lane == 0) warp_sums[warp] = s;
    __syncthreads();

    if (warp == 0) {
        float bs = (lane < (TPB >> 5)) ? warp_sums[lane] : 0.0f;
        #pragma unroll
        for (int o = 4; o > 0; o >>= 1)
            bs += __shfl_xor_sync(0xFFFFFFFFu, bs, o);
        if (lane == 0) g_part[blockIdx.x] = bs;
    }

    // Elect the last block to finish (threadfence-reduction pattern).
    __shared__ bool is_last;
    __threadfence();
    if (threadIdx.x == 0) {
        unsigned int c = atomicAdd(&g_count, 1u);
        is_last = (c == gridDim.x - 1);
    }
    __syncthreads();

    if (is_last) {
        double d = 0.0;
        for (int i = threadIdx.x; i < (int)gridDim.x; i += TPB)
            d += (double)g_part[i];

        #pragma unroll
        for (int o = 16; o > 0; o >>= 1)
            d += __shfl_xor_sync(0xFFFFFFFFu, d, o);

        __shared__ double dwarp[TPB / 32];
        if (lane == 0) dwarp[warp] = d;
        __syncthreads();
        if (warp == 0) {
            double bd = (lane < (TPB >> 5)) ? dwarp[lane] : 0.0;
            #pragma unroll
            for (int o = 4; o > 0; o >>= 1)
                bd += __shfl_xor_sync(0xFFFFFFFFu, bd, o);
            if (lane == 0) {
                out[0] = (float)(-bd * (1.0 / 256.0));
                g_count = 0;  // self-reset for next graph replay
            }
        }
    }
}

extern "C" void kernel_launch(void* const* d_in, const int* in_sizes, int n_in,
                              void* d_out, int out_size)
{
    const float* pred = (const float*)d_in[0];
    const unsigned char* mask = (const unsigned char*)d_in[1];
    float* out = (float*)d_out;

    int n = in_sizes[1];                       // 4,194,304 expected

    int blocks = (n + TPB * ILP - 1) / (TPB * ILP);  // 2048 for n=4M
    if (blocks > MAX_BLOCKS) blocks = MAX_BLOCKS;    // fallback path handles rest
    if (blocks < 1) blocks = 1;

    nll_fused_kernel<<<blocks, TPB>>>(pred, mask, out, n);
}